// round 15
// baseline (speedup 1.0000x reference)
#include <cuda_runtime.h>
#include <math.h>

#define BB 16
#define LL 1024
#define DD 16
#define MM 16
#define KK 8
#define E2 66   // edge hidden = 2*(2*DIM+1)

typedef unsigned long long ull;

// ---- scratch (allocation-free: __device__ globals) ----
__device__ float g_coors[2][BB*LL*3];
__device__ float g_feats[2][BB*LL*DD];
__device__ int   g_knn[BB*LL*KK];
__device__ float g_Pa[BB*LL*E2];
__device__ float g_Pb[BB*LL*E2];
__device__ int   g_wide;   // 1 if integer inputs are int64 (detected at runtime)

__device__ __forceinline__ int ld_int(const int* __restrict__ p, int i){
    return g_wide ? p[2*i] : p[i];
}

// branch-free silu: for x << 0, e^-x -> inf, x/inf -> -0 (correct limit)
__device__ __forceinline__ float silu_f(float x){
    return __fdividef(x, 1.0f + __expf(-x));
}

__device__ __forceinline__ float dot4(float4 a, float4 b){
    return a.x*b.x + a.y*b.y + a.z*b.z + a.w*b.w;
}

// ---- packed f32x2 helpers (FFMA2: only reachable via PTX) ----
__device__ __forceinline__ void fma2(ull& d, ull a, ull b){
    asm("fma.rn.f32x2 %0, %1, %2, %0;" : "+l"(d) : "l"(a), "l"(b));
}
__device__ __forceinline__ ull pack2(float x, float y){
    ull r; asm("mov.b64 %0, {%1, %2};" : "=l"(r) : "f"(x), "f"(y)); return r;
}
__device__ __forceinline__ float2 unpack2(ull v){
    float2 r; asm("mov.b64 {%0, %1}, %2;" : "=f"(r.x), "=f"(r.y) : "l"(v)); return r;
}

// ---------------- init (+ int-width detect)
__global__ void k_init(const float* __restrict__ coords, const int* __restrict__ residues,
                       const float* __restrict__ tok, const float* __restrict__ pos,
                       const int* __restrict__ lengths){
    int t = blockIdx.x*blockDim.x + threadIdx.x;
    if (t >= BB*LL) return;
    int wide = (lengths[1] == 0) ? 1 : 0;   // lengths in [512,1024]; 0 => int64 high word
    if (t == 0) g_wide = wide;
    int i = t & (LL-1);
    int r = wide ? residues[2*t] : residues[t];
#pragma unroll
    for (int c = 0; c < DD; c++)
        g_feats[0][t*DD + c] = tok[r*DD + c] + pos[i*DD + c];
    g_coors[0][t*3+0] = coords[t*3+0];
    g_coors[0][t*3+1] = coords[t*3+1];
    g_coors[0][t*3+2] = coords[t*3+2];
}

// top-8 insertion (strict '<' keeps ascending-j stability within a scan)
__device__ __forceinline__ void ins8(float (&val)[KK], int (&idx)[KK], float r, int j){
    if (r < val[KK-1]) {
        val[KK-1] = r; idx[KK-1] = j;
#pragma unroll
        for (int q = KK-1; q > 0; q--) {
            if (val[q] < val[q-1]) {
                float tv = val[q]; val[q] = val[q-1]; val[q-1] = tv;
                int   ti = idx[q]; idx[q] = idx[q-1]; idx[q-1] = ti;
            }
        }
    }
}

// ---------------- fused kNN (blocks 0..511) + Pa/Pb precompute (blocks 512..767)
// kNN: 32 rows/block, warp owns 4 rows, 8 lanes/row (j chunks of 128).
// Per-lane register top-8, then an 8-lane shuffle pop-merge with (val, j)
// ordering — ties prefer lower j == jax top_k ascending-index tie-break.
// Then the virtual-invalid 1e5 merge (reference candidate semantics, see R6).
__global__ void __launch_bounds__(256) k_knnpre(int bin, const int* __restrict__ lengths,
                                                const float* __restrict__ ew1,
                                                const float* __restrict__ eb1, int d){
    int tid = threadIdx.x;
    if (blockIdx.x < 512) {
        __shared__ __align__(16) float4 sc4[LL];
        int b = blockIdx.x >> 5;
        int chunk = blockIdx.x & 31;
        const float* cb = &g_coors[bin][b*LL*3];
        for (int t = tid; t < LL; t += 256)
            sc4[t] = make_float4(cb[t*3], cb[t*3+1], cb[t*3+2], 0.0f);
        __syncthreads();
        int len  = ld_int(lengths, b);
        int lane = tid & 31;
        int warp = tid >> 5;
        int r4   = lane >> 3;   // row within warp (0..3)
        int q    = lane & 7;    // j-chunk (0..7)
        int i    = chunk*32 + warp*4 + r4;
        int row  = b*LL + i;

        float val[KK]; int idx[KK];
#pragma unroll
        for (int k = 0; k < KK; k++){ val[k] = 3.0e38f; idx[k] = i; }

        if (i < len) {
            float4 ci = sc4[i];
            int lo = q*128;
            int hi = min(lo + 128, len);
            int m1 = min(hi, max(lo, i-1));     // end of pure region 1
            int m2 = max(lo, min(hi, i+2));     // start of pure region 3
#pragma unroll 4
            for (int j = lo; j < m1; j++) {
                float4 cj = sc4[j];
                float dx = ci.x - cj.x, dy = ci.y - cj.y, dz = ci.z - cj.z;
                float rr = __fadd_rn(__fadd_rn(__fmul_rn(dx,dx), __fmul_rn(dy,dy)), __fmul_rn(dz,dz));
                ins8(val, idx, rr, j);
            }
            for (int j = m1; j < min(hi, i+2); j++) {   // specials: j in {i-1, i, i+1}
                float rr = (j == i) ? -1.0f : 0.0f;
                ins8(val, idx, rr, j);
            }
#pragma unroll 4
            for (int j = m2; j < hi; j++) {
                float4 cj = sc4[j];
                float dx = ci.x - cj.x, dy = ci.y - cj.y, dz = ci.z - cj.z;
                float rr = __fadd_rn(__fadd_rn(__fmul_rn(dx,dx), __fmul_rn(dy,dy)), __fmul_rn(dz,dz));
                ins8(val, idx, rr, j);
            }
        }

        // ---- 8-lane pop-merge (all lanes participate; heads at [0], shift on win)
        float vv[KK]; int vi[KK];
#pragma unroll
        for (int k = 0; k < KK; k++) {
            float v = val[0]; int jj = idx[0];
#pragma unroll
            for (int off = 4; off > 0; off >>= 1) {
                float ov = __shfl_xor_sync(0xffffffffu, v,  off, 8);
                int   oj = __shfl_xor_sync(0xffffffffu, jj, off, 8);
                if (ov < v || (ov == v && oj < jj)) { v = ov; jj = oj; }
            }
            vv[k] = v; vi[k] = jj;
            bool win = (val[0] == v) && (idx[0] == jj);
            if (win) {
#pragma unroll
                for (int s = 0; s < KK-1; s++) { val[s] = val[s+1]; idx[s] = idx[s+1]; }
                val[KK-1] = 3.0e38f; idx[KK-1] = i;
            }
        }

        // ---- virtual-invalid 1e5 merge (head-shift walk; exact semantics of R6)
        int fi[KK];
        if (i < len) {
            int inv = len;
#pragma unroll
            for (int k = 0; k < KK; k++) {
                bool take = (inv >= LL) || (vv[0] <= 1.0e5f);
                if (take) {
                    fi[k] = vi[0];
#pragma unroll
                    for (int s = 0; s < KK-1; s++) { vv[s] = vv[s+1]; vi[s] = vi[s+1]; }
                    vv[KK-1] = 3.0e38f;
                } else {
                    fi[k] = inv++;
                }
            }
        } else {
#pragma unroll
            for (int k = 0; k < KK; k++) fi[k] = i;
        }

        if (q == 0) {
            int4* dst = (int4*)&g_knn[row*KK];
            dst[0] = make_int4(fi[0], fi[1], fi[2], fi[3]);
            dst[1] = make_int4(fi[4], fi[5], fi[6], fi[7]);
        }
    } else {
        // ---- pre: Pa = feats@W1[rows 0:16]+b1 ; Pb = feats@W1[rows 16:32]
        __shared__ __align__(16) float s_waT[E2][20];
        __shared__ __align__(16) float s_wbT[E2][20];
        __shared__ __align__(16) float s_b[E2+2];
        __shared__ __align__(16) float s_f[64*DD];
        const float* w = ew1 + d*33*E2;
        for (int t = tid; t < 16*E2; t += 256) {
            int c = t / E2, n = t - c*E2;
            s_waT[n][c] = w[c*E2 + n];
            s_wbT[n][c] = w[(16+c)*E2 + n];
        }
        for (int t = tid; t < E2; t += 256) s_b[t] = eb1[d*E2 + t];
        int row0 = (blockIdx.x - 512)*64;
        const float* fsrc = &g_feats[bin][row0*DD];
        for (int t = tid; t < 64*DD; t += 256) s_f[t] = fsrc[t];
        __syncthreads();
        float* pa = &g_Pa[(size_t)row0*E2];
        float* pb = &g_Pb[(size_t)row0*E2];
        for (int t = tid; t < 64*E2; t += 256) {
            int r = t / E2, n = t - r*E2;
            const float4* fr = (const float4*)&s_f[r*DD];
            const float4* wa = (const float4*)&s_waT[n][0];
            const float4* wb = (const float4*)&s_wbT[n][0];
            float a = s_b[n], p = 0.0f;
#pragma unroll
            for (int qq = 0; qq < 4; qq++) {
                float4 fv = fr[qq];
                float4 av = wa[qq], bv = wb[qq];
                a += fv.x*av.x + fv.y*av.y + fv.z*av.z + fv.w*av.w;
                p += fv.x*bv.x + fv.y*bv.y + fv.z*bv.z + fv.w*bv.w;
            }
            pa[t] = a;
            pb[t] = p;
        }
    }
}

// ---------------- fused layer: warp-per-row, edge-batched, f32x2 inner math
#define HSTR 76
#define MSTR 20
__global__ void __launch_bounds__(256) k_layer(
    int bin, int d,
    const int* __restrict__ lengths,
    const float* __restrict__ ew1,
    const float* __restrict__ ew2, const float* __restrict__ eb2,
    const float* __restrict__ cw1, const float* __restrict__ cb1,
    const float* __restrict__ cw2, const float* __restrict__ cb2,
    const float* __restrict__ lng, const float* __restrict__ lnb,
    const float* __restrict__ nw1, const float* __restrict__ nb1,
    const float* __restrict__ nw2, const float* __restrict__ nb2)
{
    __shared__ __align__(16) float s_w1rd[E2+2];
    __shared__ __align__(16) float s_W2[E2*MM];      // [n][c]
    __shared__ __align__(16) float s_b2[MM];
    __shared__ __align__(16) float s_cW1T[64][20];   // [u][0:16)=cW1T, [16]=cb1, [17]=cW2
    __shared__ float s_cb2;
    __shared__ __align__(16) float s_nW1T[32][36];   // [l][t]
    __shared__ __align__(16) float s_nb1[32];
    __shared__ __align__(16) float s_nW2T[16][36];   // [c][u]
    __shared__ __align__(16) float s_nb2[MM];
    __shared__ __align__(16) float s_g[DD], s_bta[DD];
    __shared__ __align__(16) float s_h[8][KK*HSTR];
    __shared__ __align__(16) float s_m[8][KK*MSTR];
    __shared__ __align__(16) float s_nin[8][32];
    __shared__ __align__(16) float s_hid[8][32];

    int tid = threadIdx.x;
    for (int t = tid; t < E2; t += 256) s_w1rd[t] = ew1[d*33*E2 + 32*E2 + t];
    for (int t = tid; t < E2*MM; t += 256) s_W2[t] = ew2[d*E2*MM + t];
    for (int t = tid; t < MM; t += 256) s_b2[t] = eb2[d*MM + t];
    for (int t = tid; t < MM*64; t += 256) {
        int c2 = t >> 6, u = t & 63;
        s_cW1T[u][c2] = cw1[d*MM*64 + t];
    }
    for (int t = tid; t < 64; t += 256) { s_cW1T[t][16] = cb1[d*64 + t]; s_cW1T[t][17] = cw2[d*64 + t]; }
    if (tid == 0) s_cb2 = cb2[d];
    for (int t = tid; t < 32*32; t += 256) {
        int tr = t >> 5, l = t & 31;
        s_nW1T[l][tr] = nw1[d*32*32 + t];
    }
    for (int t = tid; t < 32; t += 256) s_nb1[t] = nb1[d*32 + t];
    for (int t = tid; t < 32*MM; t += 256) {
        int u = t >> 4, c = t & 15;
        s_nW2T[c][u] = nw2[d*32*MM + t];
    }
    for (int t = tid; t < MM; t += 256) { s_nb2[t] = nb2[d*MM + t]; s_g[t] = lng[d*DD + t]; s_bta[t] = lnb[d*DD + t]; }
    __syncthreads();

    int w    = tid >> 5;
    int lane = tid & 31;
    int row  = blockIdx.x*8 + w;
    int b    = row >> 10;
    int i    = row & (LL-1);
    int len  = ld_int(lengths, b);
    bool vrow = (i < len);

    const float* coorsIn  = g_coors[bin];
    float*       coorsOut = g_coors[bin^1];
    const float* featsIn  = g_feats[bin];
    float*       featsOut = g_feats[bin^1];

    int c    = lane & 15;
    int half = lane >> 4;
    int e    = lane >> 2;
    int q    = lane & 3;

    float fcv = featsIn[row*DD + c];
    float cix = coorsIn[row*3+0], ciy = coorsIn[row*3+1], ciz = coorsIn[row*3+2];

    float ax = 0.0f, ay = 0.0f, az = 0.0f;
    float4 mi4 = make_float4(0.f, 0.f, 0.f, 0.f);

    float* hW = &s_h[w][0];
    float* mW = &s_m[w][0];

    if (vrow) {
        int kk = lane & 7;
        int j  = g_knn[row*KK + kk];
        float maskf = (j < len) ? 1.0f : 0.0f;
        int gj = b*LL + j;
        float dxk = cix - coorsIn[gj*3+0];
        float dyk = ciy - coorsIn[gj*3+1];
        float dzk = ciz - coorsIn[gj*3+2];
        float rdk = __fadd_rn(__fadd_rn(__fmul_rn(dxk,dxk), __fmul_rn(dyk,dyk)), __fmul_rn(dzk,dzk));

        // ---- phase 1: h for all 8 edges
        const float* Pa = &g_Pa[(size_t)row*E2];
        float pa0 = Pa[lane], pa1 = Pa[lane+32];
        float pa2 = (lane < 2) ? Pa[lane+64] : 0.0f;
        float rw0 = s_w1rd[lane], rw1 = s_w1rd[lane+32];
        float rw2 = (lane < 2) ? s_w1rd[lane+64] : 0.0f;
#pragma unroll
        for (int ee = 0; ee < KK; ee++) {
            float rd = __shfl_sync(0xffffffffu, rdk, ee);
            int   gje = __shfl_sync(0xffffffffu, gj,  ee);
            const float* Pb = &g_Pb[(size_t)gje*E2];
            hW[ee*HSTR + lane]    = silu_f(pa0 + Pb[lane]    + rd*rw0);
            hW[ee*HSTR + lane+32] = silu_f(pa1 + Pb[lane+32] + rd*rw1);
            if (lane < 2)
                hW[ee*HSTR + lane+64] = silu_f(pa2 + Pb[lane+64] + rd*rw2);
        }
        __syncwarp();

        // ---- phase 2: m[e][4q..4q+3] = silu(h[e] @ W2 + b2) * mask  (f32x2)
        {
            const ulonglong2* w2p = (const ulonglong2*)s_W2;   // row n at n*4, lane chunk +q
            const float4* h4 = (const float4*)&hW[e*HSTR];
            ull acc01 = pack2(s_b2[4*q],   s_b2[4*q+1]);
            ull acc23 = pack2(s_b2[4*q+2], s_b2[4*q+3]);
#pragma unroll
            for (int g = 0; g < 16; g++) {
                float4 hh = h4[g];
                ulonglong2 wv0 = w2p[(4*g+0)*4 + q];
                ull hp = pack2(hh.x, hh.x);
                fma2(acc01, hp, wv0.x); fma2(acc23, hp, wv0.y);
                ulonglong2 wv1 = w2p[(4*g+1)*4 + q];
                hp = pack2(hh.y, hh.y);
                fma2(acc01, hp, wv1.x); fma2(acc23, hp, wv1.y);
                ulonglong2 wv2 = w2p[(4*g+2)*4 + q];
                hp = pack2(hh.z, hh.z);
                fma2(acc01, hp, wv2.x); fma2(acc23, hp, wv2.y);
                ulonglong2 wv3 = w2p[(4*g+3)*4 + q];
                hp = pack2(hh.w, hh.w);
                fma2(acc01, hp, wv3.x); fma2(acc23, hp, wv3.y);
            }
            float h64 = hW[e*HSTR + 64], h65 = hW[e*HSTR + 65];
            ulonglong2 wv64 = w2p[64*4 + q];
            ull hp = pack2(h64, h64);
            fma2(acc01, hp, wv64.x); fma2(acc23, hp, wv64.y);
            ulonglong2 wv65 = w2p[65*4 + q];
            hp = pack2(h65, h65);
            fma2(acc01, hp, wv65.x); fma2(acc23, hp, wv65.y);

            float2 a01 = unpack2(acc01), a23 = unpack2(acc23);
            float me = __shfl_sync(0xffffffffu, maskf, e);
            float4 mv;
            mv.x = silu_f(a01.x) * me;
            mv.y = silu_f(a01.y) * me;
            mv.z = silu_f(a23.x) * me;
            mv.w = silu_f(a23.y) * me;
            *(float4*)&mW[e*MSTR + 4*q] = mv;

            mi4 = mv;
#pragma unroll
            for (int off = 4; off <= 16; off <<= 1) {
                mi4.x += __shfl_xor_sync(0xffffffffu, mi4.x, off);
                mi4.y += __shfl_xor_sync(0xffffffffu, mi4.y, off);
                mi4.z += __shfl_xor_sync(0xffffffffu, mi4.z, off);
                mi4.w += __shfl_xor_sync(0xffffffffu, mi4.w, off);
            }
        }
        __syncwarp();

        // ---- phase 3: coors MLP (f32x2); lane (e,q) handles u = 4t+q
        {
            const float4* m4 = (const float4*)&mW[e*MSTR];
            float4 mr0 = m4[0], mr1 = m4[1], mr2 = m4[2], mr3 = m4[3];
            ull mp0 = pack2(mr0.x, mr0.y), mp1 = pack2(mr0.z, mr0.w);
            ull mp2 = pack2(mr1.x, mr1.y), mp3 = pack2(mr1.z, mr1.w);
            ull mp4 = pack2(mr2.x, mr2.y), mp5 = pack2(mr2.z, mr2.w);
            ull mp6 = pack2(mr3.x, mr3.y), mp7 = pack2(mr3.z, mr3.w);
            const ulonglong2* cwp = (const ulonglong2*)s_cW1T;   // row u at u*5
            float wacc = 0.0f;
#pragma unroll
            for (int t = 0; t < 16; t++) {
                int u = 4*t + q;
                ulonglong2 w0 = cwp[u*5+0];
                ulonglong2 w1 = cwp[u*5+1];
                ulonglong2 w4 = cwp[u*5+4];          // (cb1[u], cW2[u], pad, pad)
                float2 cc = unpack2(w4.x);
                ull s01 = pack2(cc.x, 0.0f);
                fma2(s01, mp0, w0.x); fma2(s01, mp1, w0.y);
                fma2(s01, mp2, w1.x); fma2(s01, mp3, w1.y);
                ulonglong2 w2v = cwp[u*5+2];
                ulonglong2 w3 = cwp[u*5+3];
                fma2(s01, mp4, w2v.x); fma2(s01, mp5, w2v.y);
                fma2(s01, mp6, w3.x);  fma2(s01, mp7, w3.y);
                float2 sv = unpack2(s01);
                wacc += silu_f(sv.x + sv.y) * cc.y;
            }
            wacc += __shfl_xor_sync(0xffffffffu, wacc, 1);
            wacc += __shfl_xor_sync(0xffffffffu, wacc, 2);
            float wk = (__shfl_sync(0xffffffffu, wacc, 4*kk) + s_cb2) * maskf;
            float tx = wk*dxk, ty = wk*dyk, tz = wk*dzk;
#pragma unroll
            for (int off = 1; off <= 4; off <<= 1) {
                tx += __shfl_xor_sync(0xffffffffu, tx, off);
                ty += __shfl_xor_sync(0xffffffffu, ty, off);
                tz += __shfl_xor_sync(0xffffffffu, tz, off);
            }
            ax = tx; ay = ty; az = tz;
        }
    }

    if (lane == 0) {
        coorsOut[row*3+0] = cix + ax;
        coorsOut[row*3+1] = ciy + ay;
        coorsOut[row*3+2] = ciz + az;
    }

    // ---- phase 4: LayerNorm + node MLP (all rows)
    float s = fcv;
#pragma unroll
    for (int off = 8; off > 0; off >>= 1) s += __shfl_xor_sync(0xffffffffu, s, off);
    float mu = s * (1.0f/16.0f);
    float dv = fcv - mu;
    float v = dv*dv;
#pragma unroll
    for (int off = 8; off > 0; off >>= 1) v += __shfl_xor_sync(0xffffffffu, v, off);
    float var = v * (1.0f/16.0f);
    float normed = dv * rsqrtf(var + 1e-5f) * s_g[c] + s_bta[c];

    if (half == 0) s_nin[w][c] = normed;
    if (lane < 4)  *(float4*)&s_nin[w][16 + 4*q] = mi4;
    __syncwarp();

    {
        const ulonglong2* nin2 = (const ulonglong2*)&s_nin[w][0];
        const ulonglong2* w1r2 = (const ulonglong2*)&s_nW1T[lane][0];
        ull acc = pack2(s_nb1[lane], 0.0f);
#pragma unroll
        for (int g = 0; g < 8; g++) {
            ulonglong2 nv = nin2[g];
            ulonglong2 wv = w1r2[g];
            fma2(acc, nv.x, wv.x);
            fma2(acc, nv.y, wv.y);
        }
        float2 av = unpack2(acc);
        s_hid[w][lane] = silu_f(av.x + av.y);
    }
    __syncwarp();

    {
        const float4* hid4 = (const float4*)&s_hid[w][16*half];
        const float4* w2r  = (const float4*)&s_nW2T[c][16*half];
        float o = 0.0f;
#pragma unroll
        for (int g2 = 0; g2 < 4; g2++) o += dot4(hid4[g2], w2r[g2]);
        o += __shfl_xor_sync(0xffffffffu, o, 16);
        if (half == 0)
            featsOut[row*DD + c] = fcv + o + s_nb2[c];
    }
}

// ---------------- final projection: delta = feats @ final_w + final_b
__global__ void k_final(const float* __restrict__ fw, const float* __restrict__ fb, float* __restrict__ out){
    int t = blockIdx.x*blockDim.x + threadIdx.x;
    if (t >= BB*LL) return;
    const float* f = &g_feats[1][t*DD];   // after 3 layers, feats live in buffer 1
    float o0 = fb[0], o1 = fb[1], o2 = fb[2];
#pragma unroll
    for (int c2 = 0; c2 < DD; c2++){
        float fc = f[c2];
        o0 += fc * fw[c2*3+0];
        o1 += fc * fw[c2*3+1];
        o2 += fc * fw[c2*3+2];
    }
    out[t*3+0] = o0; out[t*3+1] = o1; out[t*3+2] = o2;
}

extern "C" void kernel_launch(void* const* d_in, const int* in_sizes, int n_in,
                              void* d_out, int out_size){
    int I_coords=0, I_res=1, I_len=2, I_tok=3, I_pos=4,
        I_ew1=5, I_eb1=6, I_ew2=7, I_eb2=8,
        I_cw1=9, I_cb1=10, I_cw2=11, I_cb2=12,
        I_lng=13, I_lnb=14, I_nw1=15, I_nb1=16, I_nw2=17, I_nb2=18,
        I_fw=19, I_fb=20;
    if (n_in >= 21 && in_sizes[1] == 192) {
        I_coords=0; I_cb1=1; I_cb2=2; I_cw1=3; I_cw2=4;
        I_eb1=5; I_eb2=6; I_ew1=7; I_ew2=8; I_fb=9; I_fw=10; I_len=11;
        I_lnb=12; I_lng=13; I_nb1=14; I_nb2=15; I_nw1=16; I_nw2=17;
        I_pos=18; I_res=19; I_tok=20;
    }

    const float* coords   = (const float*)d_in[I_coords];
    const int*   residues = (const int*)  d_in[I_res];
    const int*   lengths  = (const int*)  d_in[I_len];
    const float* tok      = (const float*)d_in[I_tok];
    const float* pos      = (const float*)d_in[I_pos];
    const float* ew1      = (const float*)d_in[I_ew1];
    const float* eb1      = (const float*)d_in[I_eb1];
    const float* ew2      = (const float*)d_in[I_ew2];
    const float* eb2      = (const float*)d_in[I_eb2];
    const float* cw1      = (const float*)d_in[I_cw1];
    const float* cb1      = (const float*)d_in[I_cb1];
    const float* cw2      = (const float*)d_in[I_cw2];
    const float* cb2      = (const float*)d_in[I_cb2];
    const float* lng      = (const float*)d_in[I_lng];
    const float* lnb      = (const float*)d_in[I_lnb];
    const float* nw1      = (const float*)d_in[I_nw1];
    const float* nb1      = (const float*)d_in[I_nb1];
    const float* nw2      = (const float*)d_in[I_nw2];
    const float* nb2      = (const float*)d_in[I_nb2];
    const float* fw       = (const float*)d_in[I_fw];
    const float* fb       = (const float*)d_in[I_fb];
    float* out = (float*)d_out;

    k_init<<<64, 256>>>(coords, residues, tok, pos, lengths);
    for (int dd = 0; dd < 3; dd++){
        int bin = dd & 1;
        k_knnpre<<<768, 256>>>(bin, lengths, ew1, eb1, dd);
        k_layer<<<BB*LL/8, 256>>>(bin, dd, lengths, ew1, ew2, eb2,
                                  cw1, cb1, cw2, cb2, lng, lnb,
                                  nw1, nb1, nw2, nb2);
    }
    k_final<<<64, 256>>>(fw, fb, out);
}

// round 16
// speedup vs baseline: 1.3128x; 1.3128x over previous
#include <cuda_runtime.h>
#include <math.h>

#define BB 16
#define LL 1024
#define DD 16
#define MM 16
#define KK 8
#define E2 66   // edge hidden = 2*(2*DIM+1)

typedef unsigned long long ull;

// ---- scratch (allocation-free: __device__ globals) ----
__device__ float g_coors[2][BB*LL*3];
__device__ float g_feats[2][BB*LL*DD];
__device__ int   g_knn[BB*LL*KK];
__device__ float g_Pa[BB*LL*E2];
__device__ float g_Pb[BB*LL*E2];
__device__ int   g_wide;   // 1 if integer inputs are int64 (detected at runtime)

__device__ __forceinline__ int ld_int(const int* __restrict__ p, int i){
    return g_wide ? p[2*i] : p[i];
}

// branch-free silu: for x << 0, e^-x -> inf, x/inf -> -0 (correct limit)
__device__ __forceinline__ float silu_f(float x){
    return __fdividef(x, 1.0f + __expf(-x));
}

__device__ __forceinline__ float dot4(float4 a, float4 b){
    return a.x*b.x + a.y*b.y + a.z*b.z + a.w*b.w;
}

// ---- packed f32x2 helpers (FFMA2: only reachable via PTX) ----
__device__ __forceinline__ void fma2(ull& d, ull a, ull b){
    asm("fma.rn.f32x2 %0, %1, %2, %0;" : "+l"(d) : "l"(a), "l"(b));
}
__device__ __forceinline__ ull pack2(float x, float y){
    ull r; asm("mov.b64 %0, {%1, %2};" : "=l"(r) : "f"(x), "f"(y)); return r;
}
__device__ __forceinline__ float2 unpack2(ull v){
    float2 r; asm("mov.b64 {%0, %1}, %2;" : "=f"(r.x), "=f"(r.y) : "l"(v)); return r;
}

// ---------------- init (+ int-width detect)
__global__ void k_init(const float* __restrict__ coords, const int* __restrict__ residues,
                       const float* __restrict__ tok, const float* __restrict__ pos,
                       const int* __restrict__ lengths){
    int t = blockIdx.x*blockDim.x + threadIdx.x;
    if (t >= BB*LL) return;
    int wide = (lengths[1] == 0) ? 1 : 0;   // lengths in [512,1024]; 0 => int64 high word
    if (t == 0) g_wide = wide;
    int i = t & (LL-1);
    int r = wide ? residues[2*t] : residues[t];
#pragma unroll
    for (int c = 0; c < DD; c++)
        g_feats[0][t*DD + c] = tok[r*DD + c] + pos[i*DD + c];
    g_coors[0][t*3+0] = coords[t*3+0];
    g_coors[0][t*3+1] = coords[t*3+1];
    g_coors[0][t*3+2] = coords[t*3+2];
}

// top-8 insertion (strict '<' keeps ascending-j stability within a scan)
__device__ __forceinline__ void ins8(float (&val)[KK], int (&idx)[KK], float r, int j){
    if (r < val[KK-1]) {
        val[KK-1] = r; idx[KK-1] = j;
#pragma unroll
        for (int q = KK-1; q > 0; q--) {
            if (val[q] < val[q-1]) {
                float tv = val[q]; val[q] = val[q-1]; val[q-1] = tv;
                int   ti = idx[q]; idx[q] = idx[q-1]; idx[q-1] = ti;
            }
        }
    }
}

#define NS 8      // j-splits per row
#define RB 32     // rows per knn block
#define MS 9      // merge smem stride (coprime with 32 -> conflict-free)

// ---------------- fused kNN (blocks 0..511) + Pa/Pb precompute (blocks 512..767)
// kNN: 32 rows/block, 8 threads/row. [0,len) is divided EVENLY among the 8
// threads (csz = ceil(len/8)) so no thread idles — chunks remain disjoint
// ascending-j ranges, so the merge's lower-chunk-preferred strict '<' ties
// still equal jax top_k's ascending-index tie-break. Then the
// virtual-invalid 1e5 merge (reference candidate semantics, see R6).
__global__ void __launch_bounds__(256) k_knnpre(int bin, const int* __restrict__ lengths,
                                                const float* __restrict__ ew1,
                                                const float* __restrict__ eb1, int d){
    int tid = threadIdx.x;
    if (blockIdx.x < 512) {
        __shared__ __align__(16) float4 sc4[LL];
        __shared__ float s_mv[NS*RB*MS];
        __shared__ int   s_mi[NS*RB*MS];
        int b = blockIdx.x >> 5;
        int chunk = blockIdx.x & 31;
        const float* cb = &g_coors[bin][b*LL*3];
        for (int t = tid; t < LL; t += 256)
            sc4[t] = make_float4(cb[t*3], cb[t*3+1], cb[t*3+2], 0.0f);
        __syncthreads();
        int len = ld_int(lengths, b);
        int r  = tid & (RB-1);
        int q  = tid >> 5;          // 0..7
        int i  = chunk*RB + r;

        float val[KK]; int idx[KK];
#pragma unroll
        for (int k = 0; k < KK; k++){ val[k] = 3.0e38f; idx[k] = i; }

        if (i < len) {
            float4 ci = sc4[i];
            int csz = (len + NS - 1) >> 3;      // even split of [0,len)
            int lo = q*csz;
            int hi = min(lo + csz, len);
            int m1 = min(hi, max(lo, i-1));     // end of pure region 1
            int m2 = max(lo, min(hi, i+2));     // start of pure region 3
#pragma unroll 4
            for (int j = lo; j < m1; j++) {
                float4 cj = sc4[j];
                float dx = ci.x - cj.x, dy = ci.y - cj.y, dz = ci.z - cj.z;
                float rr = __fadd_rn(__fadd_rn(__fmul_rn(dx,dx), __fmul_rn(dy,dy)), __fmul_rn(dz,dz));
                ins8(val, idx, rr, j);
            }
            for (int j = m1; j < min(hi, i+2); j++) {   // specials: j in {i-1, i, i+1}
                float rr = (j == i) ? -1.0f : 0.0f;
                ins8(val, idx, rr, j);
            }
#pragma unroll 4
            for (int j = m2; j < hi; j++) {
                float4 cj = sc4[j];
                float dx = ci.x - cj.x, dy = ci.y - cj.y, dz = ci.z - cj.z;
                float rr = __fadd_rn(__fadd_rn(__fmul_rn(dx,dx), __fmul_rn(dy,dy)), __fmul_rn(dz,dz));
                ins8(val, idx, rr, j);
            }
        }
#pragma unroll
        for (int k = 0; k < KK; k++) {
            s_mv[(q*RB + r)*MS + k] = val[k];
            s_mi[(q*RB + r)*MS + k] = idx[k];
        }
        __syncthreads();

        if (tid < RB) {
            int rr = tid;
            int ii2 = chunk*RB + rr;
            int row = b*LL + ii2;
            float vv[KK]; int vi[KK];
            int p[NS];
#pragma unroll
            for (int qq = 0; qq < NS; qq++) p[qq] = 0;
#pragma unroll
            for (int k = 0; k < KK; k++) {
                int best = 0;
                float bv = s_mv[(0*RB+rr)*MS + p[0]];
#pragma unroll
                for (int qq = 1; qq < NS; qq++) {
                    float vq = s_mv[(qq*RB+rr)*MS + p[qq]];
                    if (vq < bv) { bv = vq; best = qq; }
                }
                vv[k] = bv;
#pragma unroll
                for (int qq = 0; qq < NS; qq++)
                    if (best == qq) { vi[k] = s_mi[(qq*RB+rr)*MS + p[qq]]; p[qq]++; }
            }
            if (ii2 < len) {
                // merge with virtual invalid candidates (value exactly 1e5, idx len..1023)
                int v = 0, inv = len;
                int fi[KK];
#pragma unroll
                for (int k = 0; k < KK; k++) {
                    if (inv >= LL || vv[v] <= 1.0e5f) { fi[k] = vi[v]; v++; }
                    else                              { fi[k] = inv++; }
                }
#pragma unroll
                for (int k = 0; k < KK; k++) vi[k] = fi[k];
            }
#pragma unroll
            for (int k = 0; k < KK; k++) g_knn[row*KK + k] = vi[k];
        }
    } else {
        // ---- pre: Pa = feats@W1[rows 0:16]+b1 ; Pb = feats@W1[rows 16:32]
        __shared__ __align__(16) float s_waT[E2][20];
        __shared__ __align__(16) float s_wbT[E2][20];
        __shared__ __align__(16) float s_b[E2+2];
        __shared__ __align__(16) float s_f[64*DD];
        const float* w = ew1 + d*33*E2;
        for (int t = tid; t < 16*E2; t += 256) {
            int c = t / E2, n = t - c*E2;
            s_waT[n][c] = w[c*E2 + n];
            s_wbT[n][c] = w[(16+c)*E2 + n];
        }
        for (int t = tid; t < E2; t += 256) s_b[t] = eb1[d*E2 + t];
        int row0 = (blockIdx.x - 512)*64;
        const float* fsrc = &g_feats[bin][row0*DD];
        for (int t = tid; t < 64*DD; t += 256) s_f[t] = fsrc[t];
        __syncthreads();
        float* pa = &g_Pa[(size_t)row0*E2];
        float* pb = &g_Pb[(size_t)row0*E2];
        for (int t = tid; t < 64*E2; t += 256) {
            int r = t / E2, n = t - r*E2;
            const float4* fr = (const float4*)&s_f[r*DD];
            const float4* wa = (const float4*)&s_waT[n][0];
            const float4* wb = (const float4*)&s_wbT[n][0];
            float a = s_b[n], p = 0.0f;
#pragma unroll
            for (int qq = 0; qq < 4; qq++) {
                float4 fv = fr[qq];
                float4 av = wa[qq], bv = wb[qq];
                a += fv.x*av.x + fv.y*av.y + fv.z*av.z + fv.w*av.w;
                p += fv.x*bv.x + fv.y*bv.y + fv.z*bv.z + fv.w*bv.w;
            }
            pa[t] = a;
            pb[t] = p;
        }
    }
}

// ---------------- fused layer: warp-per-row, edge-batched, f32x2 inner math
#define HSTR 76
#define MSTR 20
__global__ void __launch_bounds__(256) k_layer(
    int bin, int d,
    const int* __restrict__ lengths,
    const float* __restrict__ ew1,
    const float* __restrict__ ew2, const float* __restrict__ eb2,
    const float* __restrict__ cw1, const float* __restrict__ cb1,
    const float* __restrict__ cw2, const float* __restrict__ cb2,
    const float* __restrict__ lng, const float* __restrict__ lnb,
    const float* __restrict__ nw1, const float* __restrict__ nb1,
    const float* __restrict__ nw2, const float* __restrict__ nb2)
{
    __shared__ __align__(16) float s_w1rd[E2+2];
    __shared__ __align__(16) float s_W2[E2*MM];      // [n][c]
    __shared__ __align__(16) float s_b2[MM];
    __shared__ __align__(16) float s_cW1T[64][20];   // [u][0:16)=cW1T, [16]=cb1, [17]=cW2
    __shared__ float s_cb2;
    __shared__ __align__(16) float s_nW1T[32][36];   // [l][t]
    __shared__ __align__(16) float s_nb1[32];
    __shared__ __align__(16) float s_nW2T[16][36];   // [c][u]
    __shared__ __align__(16) float s_nb2[MM];
    __shared__ __align__(16) float s_g[DD], s_bta[DD];
    __shared__ __align__(16) float s_h[8][KK*HSTR];
    __shared__ __align__(16) float s_m[8][KK*MSTR];
    __shared__ __align__(16) float s_nin[8][32];
    __shared__ __align__(16) float s_hid[8][32];

    int tid = threadIdx.x;
    for (int t = tid; t < E2; t += 256) s_w1rd[t] = ew1[d*33*E2 + 32*E2 + t];
    for (int t = tid; t < E2*MM; t += 256) s_W2[t] = ew2[d*E2*MM + t];
    for (int t = tid; t < MM; t += 256) s_b2[t] = eb2[d*MM + t];
    for (int t = tid; t < MM*64; t += 256) {
        int c2 = t >> 6, u = t & 63;
        s_cW1T[u][c2] = cw1[d*MM*64 + t];
    }
    for (int t = tid; t < 64; t += 256) { s_cW1T[t][16] = cb1[d*64 + t]; s_cW1T[t][17] = cw2[d*64 + t]; }
    if (tid == 0) s_cb2 = cb2[d];
    for (int t = tid; t < 32*32; t += 256) {
        int tr = t >> 5, l = t & 31;
        s_nW1T[l][tr] = nw1[d*32*32 + t];
    }
    for (int t = tid; t < 32; t += 256) s_nb1[t] = nb1[d*32 + t];
    for (int t = tid; t < 32*MM; t += 256) {
        int u = t >> 4, c = t & 15;
        s_nW2T[c][u] = nw2[d*32*MM + t];
    }
    for (int t = tid; t < MM; t += 256) { s_nb2[t] = nb2[d*MM + t]; s_g[t] = lng[d*DD + t]; s_bta[t] = lnb[d*DD + t]; }
    __syncthreads();

    int w    = tid >> 5;
    int lane = tid & 31;
    int row  = blockIdx.x*8 + w;
    int b    = row >> 10;
    int i    = row & (LL-1);
    int len  = ld_int(lengths, b);
    bool vrow = (i < len);

    const float* coorsIn  = g_coors[bin];
    float*       coorsOut = g_coors[bin^1];
    const float* featsIn  = g_feats[bin];
    float*       featsOut = g_feats[bin^1];

    int c    = lane & 15;
    int half = lane >> 4;
    int e    = lane >> 2;
    int q    = lane & 3;

    float fcv = featsIn[row*DD + c];
    float cix = coorsIn[row*3+0], ciy = coorsIn[row*3+1], ciz = coorsIn[row*3+2];

    float ax = 0.0f, ay = 0.0f, az = 0.0f;
    float4 mi4 = make_float4(0.f, 0.f, 0.f, 0.f);

    float* hW = &s_h[w][0];
    float* mW = &s_m[w][0];

    if (vrow) {
        int kk = lane & 7;
        int j  = g_knn[row*KK + kk];
        float maskf = (j < len) ? 1.0f : 0.0f;
        int gj = b*LL + j;
        float dxk = cix - coorsIn[gj*3+0];
        float dyk = ciy - coorsIn[gj*3+1];
        float dzk = ciz - coorsIn[gj*3+2];
        float rdk = __fadd_rn(__fadd_rn(__fmul_rn(dxk,dxk), __fmul_rn(dyk,dyk)), __fmul_rn(dzk,dzk));

        // ---- phase 1: h for all 8 edges
        const float* Pa = &g_Pa[(size_t)row*E2];
        float pa0 = Pa[lane], pa1 = Pa[lane+32];
        float pa2 = (lane < 2) ? Pa[lane+64] : 0.0f;
        float rw0 = s_w1rd[lane], rw1 = s_w1rd[lane+32];
        float rw2 = (lane < 2) ? s_w1rd[lane+64] : 0.0f;
#pragma unroll
        for (int ee = 0; ee < KK; ee++) {
            float rd = __shfl_sync(0xffffffffu, rdk, ee);
            int   gje = __shfl_sync(0xffffffffu, gj,  ee);
            const float* Pb = &g_Pb[(size_t)gje*E2];
            hW[ee*HSTR + lane]    = silu_f(pa0 + Pb[lane]    + rd*rw0);
            hW[ee*HSTR + lane+32] = silu_f(pa1 + Pb[lane+32] + rd*rw1);
            if (lane < 2)
                hW[ee*HSTR + lane+64] = silu_f(pa2 + Pb[lane+64] + rd*rw2);
        }
        __syncwarp();

        // ---- phase 2: m[e][4q..4q+3] = silu(h[e] @ W2 + b2) * mask  (f32x2)
        {
            const ulonglong2* w2p = (const ulonglong2*)s_W2;   // row n at n*4, lane chunk +q
            const float4* h4 = (const float4*)&hW[e*HSTR];
            ull acc01 = pack2(s_b2[4*q],   s_b2[4*q+1]);
            ull acc23 = pack2(s_b2[4*q+2], s_b2[4*q+3]);
#pragma unroll
            for (int g = 0; g < 16; g++) {
                float4 hh = h4[g];
                ulonglong2 wv0 = w2p[(4*g+0)*4 + q];
                ull hp = pack2(hh.x, hh.x);
                fma2(acc01, hp, wv0.x); fma2(acc23, hp, wv0.y);
                ulonglong2 wv1 = w2p[(4*g+1)*4 + q];
                hp = pack2(hh.y, hh.y);
                fma2(acc01, hp, wv1.x); fma2(acc23, hp, wv1.y);
                ulonglong2 wv2 = w2p[(4*g+2)*4 + q];
                hp = pack2(hh.z, hh.z);
                fma2(acc01, hp, wv2.x); fma2(acc23, hp, wv2.y);
                ulonglong2 wv3 = w2p[(4*g+3)*4 + q];
                hp = pack2(hh.w, hh.w);
                fma2(acc01, hp, wv3.x); fma2(acc23, hp, wv3.y);
            }
            float h64 = hW[e*HSTR + 64], h65 = hW[e*HSTR + 65];
            ulonglong2 wv64 = w2p[64*4 + q];
            ull hp = pack2(h64, h64);
            fma2(acc01, hp, wv64.x); fma2(acc23, hp, wv64.y);
            ulonglong2 wv65 = w2p[65*4 + q];
            hp = pack2(h65, h65);
            fma2(acc01, hp, wv65.x); fma2(acc23, hp, wv65.y);

            float2 a01 = unpack2(acc01), a23 = unpack2(acc23);
            float me = __shfl_sync(0xffffffffu, maskf, e);
            float4 mv;
            mv.x = silu_f(a01.x) * me;
            mv.y = silu_f(a01.y) * me;
            mv.z = silu_f(a23.x) * me;
            mv.w = silu_f(a23.y) * me;
            *(float4*)&mW[e*MSTR + 4*q] = mv;

            mi4 = mv;
#pragma unroll
            for (int off = 4; off <= 16; off <<= 1) {
                mi4.x += __shfl_xor_sync(0xffffffffu, mi4.x, off);
                mi4.y += __shfl_xor_sync(0xffffffffu, mi4.y, off);
                mi4.z += __shfl_xor_sync(0xffffffffu, mi4.z, off);
                mi4.w += __shfl_xor_sync(0xffffffffu, mi4.w, off);
            }
        }
        __syncwarp();

        // ---- phase 3: coors MLP (f32x2); lane (e,q) handles u = 4t+q
        {
            const float4* m4 = (const float4*)&mW[e*MSTR];
            float4 mr0 = m4[0], mr1 = m4[1], mr2 = m4[2], mr3 = m4[3];
            ull mp0 = pack2(mr0.x, mr0.y), mp1 = pack2(mr0.z, mr0.w);
            ull mp2 = pack2(mr1.x, mr1.y), mp3 = pack2(mr1.z, mr1.w);
            ull mp4 = pack2(mr2.x, mr2.y), mp5 = pack2(mr2.z, mr2.w);
            ull mp6 = pack2(mr3.x, mr3.y), mp7 = pack2(mr3.z, mr3.w);
            const ulonglong2* cwp = (const ulonglong2*)s_cW1T;   // row u at u*5
            float wacc = 0.0f;
#pragma unroll
            for (int t = 0; t < 16; t++) {
                int u = 4*t + q;
                ulonglong2 w0 = cwp[u*5+0];
                ulonglong2 w1 = cwp[u*5+1];
                ulonglong2 w4 = cwp[u*5+4];          // (cb1[u], cW2[u], pad, pad)
                float2 cc = unpack2(w4.x);
                ull s01 = pack2(cc.x, 0.0f);
                fma2(s01, mp0, w0.x); fma2(s01, mp1, w0.y);
                fma2(s01, mp2, w1.x); fma2(s01, mp3, w1.y);
                ulonglong2 w2v = cwp[u*5+2];
                ulonglong2 w3 = cwp[u*5+3];
                fma2(s01, mp4, w2v.x); fma2(s01, mp5, w2v.y);
                fma2(s01, mp6, w3.x);  fma2(s01, mp7, w3.y);
                float2 sv = unpack2(s01);
                wacc += silu_f(sv.x + sv.y) * cc.y;
            }
            wacc += __shfl_xor_sync(0xffffffffu, wacc, 1);
            wacc += __shfl_xor_sync(0xffffffffu, wacc, 2);
            float wk = (__shfl_sync(0xffffffffu, wacc, 4*kk) + s_cb2) * maskf;
            float tx = wk*dxk, ty = wk*dyk, tz = wk*dzk;
#pragma unroll
            for (int off = 1; off <= 4; off <<= 1) {
                tx += __shfl_xor_sync(0xffffffffu, tx, off);
                ty += __shfl_xor_sync(0xffffffffu, ty, off);
                tz += __shfl_xor_sync(0xffffffffu, tz, off);
            }
            ax = tx; ay = ty; az = tz;
        }
    }

    if (lane == 0) {
        coorsOut[row*3+0] = cix + ax;
        coorsOut[row*3+1] = ciy + ay;
        coorsOut[row*3+2] = ciz + az;
    }

    // ---- phase 4: LayerNorm + node MLP (all rows)
    float s = fcv;
#pragma unroll
    for (int off = 8; off > 0; off >>= 1) s += __shfl_xor_sync(0xffffffffu, s, off);
    float mu = s * (1.0f/16.0f);
    float dv = fcv - mu;
    float v = dv*dv;
#pragma unroll
    for (int off = 8; off > 0; off >>= 1) v += __shfl_xor_sync(0xffffffffu, v, off);
    float var = v * (1.0f/16.0f);
    float normed = dv * rsqrtf(var + 1e-5f) * s_g[c] + s_bta[c];

    if (half == 0) s_nin[w][c] = normed;
    if (lane < 4)  *(float4*)&s_nin[w][16 + 4*q] = mi4;
    __syncwarp();

    {
        const ulonglong2* nin2 = (const ulonglong2*)&s_nin[w][0];
        const ulonglong2* w1r2 = (const ulonglong2*)&s_nW1T[lane][0];
        ull acc = pack2(s_nb1[lane], 0.0f);
#pragma unroll
        for (int g = 0; g < 8; g++) {
            ulonglong2 nv = nin2[g];
            ulonglong2 wv = w1r2[g];
            fma2(acc, nv.x, wv.x);
            fma2(acc, nv.y, wv.y);
        }
        float2 av = unpack2(acc);
        s_hid[w][lane] = silu_f(av.x + av.y);
    }
    __syncwarp();

    {
        const float4* hid4 = (const float4*)&s_hid[w][16*half];
        const float4* w2r  = (const float4*)&s_nW2T[c][16*half];
        float o = 0.0f;
#pragma unroll
        for (int g2 = 0; g2 < 4; g2++) o += dot4(hid4[g2], w2r[g2]);
        o += __shfl_xor_sync(0xffffffffu, o, 16);
        if (half == 0)
            featsOut[row*DD + c] = fcv + o + s_nb2[c];
    }
}

// ---------------- final projection: delta = feats @ final_w + final_b
__global__ void k_final(const float* __restrict__ fw, const float* __restrict__ fb, float* __restrict__ out){
    int t = blockIdx.x*blockDim.x + threadIdx.x;
    if (t >= BB*LL) return;
    const float* f = &g_feats[1][t*DD];   // after 3 layers, feats live in buffer 1
    float o0 = fb[0], o1 = fb[1], o2 = fb[2];
#pragma unroll
    for (int c2 = 0; c2 < DD; c2++){
        float fc = f[c2];
        o0 += fc * fw[c2*3+0];
        o1 += fc * fw[c2*3+1];
        o2 += fc * fw[c2*3+2];
    }
    out[t*3+0] = o0; out[t*3+1] = o1; out[t*3+2] = o2;
}

extern "C" void kernel_launch(void* const* d_in, const int* in_sizes, int n_in,
                              void* d_out, int out_size){
    int I_coords=0, I_res=1, I_len=2, I_tok=3, I_pos=4,
        I_ew1=5, I_eb1=6, I_ew2=7, I_eb2=8,
        I_cw1=9, I_cb1=10, I_cw2=11, I_cb2=12,
        I_lng=13, I_lnb=14, I_nw1=15, I_nb1=16, I_nw2=17, I_nb2=18,
        I_fw=19, I_fb=20;
    if (n_in >= 21 && in_sizes[1] == 192) {
        I_coords=0; I_cb1=1; I_cb2=2; I_cw1=3; I_cw2=4;
        I_eb1=5; I_eb2=6; I_ew1=7; I_ew2=8; I_fb=9; I_fw=10; I_len=11;
        I_lnb=12; I_lng=13; I_nb1=14; I_nb2=15; I_nw1=16; I_nw2=17;
        I_pos=18; I_res=19; I_tok=20;
    }

    const float* coords   = (const float*)d_in[I_coords];
    const int*   residues = (const int*)  d_in[I_res];
    const int*   lengths  = (const int*)  d_in[I_len];
    const float* tok      = (const float*)d_in[I_tok];
    const float* pos      = (const float*)d_in[I_pos];
    const float* ew1      = (const float*)d_in[I_ew1];
    const float* eb1      = (const float*)d_in[I_eb1];
    const float* ew2      = (const float*)d_in[I_ew2];
    const float* eb2      = (const float*)d_in[I_eb2];
    const float* cw1      = (const float*)d_in[I_cw1];
    const float* cb1      = (const float*)d_in[I_cb1];
    const float* cw2      = (const float*)d_in[I_cw2];
    const float* cb2      = (const float*)d_in[I_cb2];
    const float* lng      = (const float*)d_in[I_lng];
    const float* lnb      = (const float*)d_in[I_lnb];
    const float* nw1      = (const float*)d_in[I_nw1];
    const float* nb1      = (const float*)d_in[I_nb1];
    const float* nw2      = (const float*)d_in[I_nw2];
    const float* nb2      = (const float*)d_in[I_nb2];
    const float* fw       = (const float*)d_in[I_fw];
    const float* fb       = (const float*)d_in[I_fb];
    float* out = (float*)d_out;

    k_init<<<64, 256>>>(coords, residues, tok, pos, lengths);
    for (int dd = 0; dd < 3; dd++){
        int bin = dd & 1;
        k_knnpre<<<768, 256>>>(bin, lengths, ew1, eb1, dd);
        k_layer<<<BB*LL/8, 256>>>(bin, dd, lengths, ew1, ew2, eb2,
                                  cw1, cb1, cw2, cb2, lng, lnb,
                                  nw1, nb1, nw2, nb2);
    }
    k_final<<<64, 256>>>(fw, fb, out);
}